// round 3
// baseline (speedup 1.0000x reference)
#include <cuda_runtime.h>
#include <cstdint>
#include <math.h>

// DenseHyperbolic fused kernel, SIMT FFMA2 path (tcgen05 unavailable: harness
// builds PTX for plain sm_100, which rejects tcgen05/.cta_group).
//
// Analytic reduction of the reference:
//   g = v'(col0=0) @ W ; out_j = Aw*g_j + Ab*bias_j ; out_0 = sqrt(c2)*cosh(.)
// where Aw/Ab are per-row scalars of Sv, Sg, dg, Sb.
//
// R1 was LDS-bound (L1 72.5%, fma 58.2%). This version restructures for
// fma-bound: 8 rows x 8 cols per thread, full-warp-broadcast A (float2 over
// k, depth-1 prefetch), conflict-free LDS.128 W reads. Target ~12 LDS
// wavefronts vs 128 fma-cycles per CTA per k-step.

constexpr int D  = 256;
constexpr int BM = 64;
constexpr int BK = 16;
constexpr int NT = 256;
constexpr int APAD = 20;          // sA row stride (floats): 16 + 4, float4-aligned

#define EPSF       1e-4f
#define ACOSH_MINF 1.0001f
#define CLIPF      8.0f

typedef unsigned long long u64;

__device__ __forceinline__ u64 pack2(float x, float y) {
    u64 r; asm("mov.b64 %0, {%1, %2};" : "=l"(r) : "f"(x), "f"(y)); return r;
}
__device__ __forceinline__ void unpack2(u64 v, float& x, float& y) {
    asm("mov.b64 {%0, %1}, %2;" : "=f"(x), "=f"(y) : "l"(v));
}
__device__ __forceinline__ void ffma2(u64& d, u64 a, u64 b) {
    asm("fma.rn.f32x2 %0, %1, %2, %0;" : "+l"(d) : "l"(a), "l"(b));
}

__global__ __launch_bounds__(NT, 2)
void dh_kernel(const float* __restrict__ V,
               const float* __restrict__ cin_p,
               const float* __restrict__ cout_p,
               const float* __restrict__ W,
               const float* __restrict__ bias,
               float* __restrict__ out, int B)
{
    __shared__ float sA[BM * APAD];      // 5 KB
    __shared__ float sW[BK * D];         // 16 KB
    __shared__ float sbias[D];
    __shared__ float svsum[BM];
    __shared__ float sred[8];
    __shared__ float sSb;

    const int tid  = threadIdx.x;
    const int row0 = blockIdx.x * BM;

    // bias -> smem; Sb = sum(bias^2)
    {
        float bv = (tid == 0) ? 0.f : __ldg(&bias[tid - 1]);
        sbias[tid] = bv;
        float sq = bv * bv;
        #pragma unroll
        for (int o = 16; o > 0; o >>= 1) sq += __shfl_xor_sync(~0u, sq, o);
        if ((tid & 31) == 0) sred[tid >> 5] = sq;
    }
    __syncthreads();
    if (tid == 0) {
        float s = 0.f;
        #pragma unroll
        for (int i = 0; i < 8; i++) s += sred[i];
        sSb = s;
    }

    const int ty = tid >> 5;     // warp id 0..7: rows ty*4..+3 and 32+ty*4..+3
    const int tx = tid & 31;     // cols tx*4..+3 and 128+tx*4..+3
    const int ar  = tid >> 2;    // A-load row
    const int ac4 = tid & 3;     // A-load float4 slot

    const int rb0 = (ty * 4) * APAD;          // sA base, row block 0
    const int rb1 = (32 + ty * 4) * APAD;     // sA base, row block 1

    // acc[i][p]: i = row (0..3 block0, 4..7 block1); p = col pair
    //   p0: (tx*4, tx*4+1)  p1: (tx*4+2, tx*4+3)
    //   p2: (128+tx*4, +1)  p3: (128+tx*4+2, +3)
    u64 acc[8][4];
    #pragma unroll
    for (int i = 0; i < 8; i++)
        #pragma unroll
        for (int p = 0; p < 4; p++) acc[i][p] = 0ull;

    float svloc = 0.f;

    for (int kt = 0; kt < D / BK; ++kt) {
        __syncthreads();
        // A tile [64 x 16]: one float4 per thread, zero time coordinate.
        {
            float4 a = *reinterpret_cast<const float4*>(
                V + (size_t)(row0 + ar) * D + kt * BK + ac4 * 4);
            if (kt == 0 && ac4 == 0) a.x = 0.f;
            svloc += a.x * a.x + a.y * a.y + a.z * a.z + a.w * a.w;
            *reinterpret_cast<float4*>(sA + ar * APAD + ac4 * 4) = a;
        }
        // W tile [16 x 256]: 4 float4 per thread, coalesced (L2-resident).
        #pragma unroll
        for (int l = 0; l < 4; ++l) {
            int p  = tid + l * NT;
            int wr = p >> 6;
            int wc = (p & 63) * 4;
            *reinterpret_cast<float4*>(sW + wr * D + wc) =
                *reinterpret_cast<const float4*>(W + (size_t)(kt * BK + wr) * D + wc);
        }
        __syncthreads();

        // A prefetch for kk2=0: 8 x float2 (2 k-values per row), warp-broadcast
        float2 af[8];
        #pragma unroll
        for (int i = 0; i < 4; ++i) {
            af[i]     = *reinterpret_cast<const float2*>(sA + rb0 + i * APAD);
            af[i + 4] = *reinterpret_cast<const float2*>(sA + rb1 + i * APAD);
        }

        #pragma unroll
        for (int kk2 = 0; kk2 < BK / 2; ++kk2) {
            float2 afn[8];
            if (kk2 < BK / 2 - 1) {
                #pragma unroll
                for (int i = 0; i < 4; ++i) {
                    afn[i]     = *reinterpret_cast<const float2*>(sA + rb0 + i * APAD + kk2 * 2 + 2);
                    afn[i + 4] = *reinterpret_cast<const float2*>(sA + rb1 + i * APAD + kk2 * 2 + 2);
                }
            }
            #pragma unroll
            for (int s = 0; s < 2; ++s) {
                const int kk = kk2 * 2 + s;
                // W frag: 2 x LDS.128, lanes contiguous -> conflict-free
                ulonglong2 wa = *reinterpret_cast<const ulonglong2*>(sW + kk * D + tx * 4);
                ulonglong2 wb = *reinterpret_cast<const ulonglong2*>(sW + kk * D + 128 + tx * 4);
                #pragma unroll
                for (int i = 0; i < 8; ++i) {
                    float av = s ? af[i].y : af[i].x;
                    u64 a2 = pack2(av, av);
                    ffma2(acc[i][0], a2, wa.x);
                    ffma2(acc[i][1], a2, wa.y);
                    ffma2(acc[i][2], a2, wb.x);
                    ffma2(acc[i][3], a2, wb.y);
                }
            }
            #pragma unroll
            for (int i = 0; i < 8; ++i) af[i] = afn[i];
        }
    }

    // Sv: reduce 4 lanes (ac4) per row.
    svloc += __shfl_xor_sync(~0u, svloc, 1);
    svloc += __shfl_xor_sync(~0u, svloc, 2);
    if (ac4 == 0) svsum[ar] = svloc;
    __syncthreads();

    const float c   = *cin_p;
    const float c2  = *cout_p;
    const float sqc = sqrtf(c);
    const float sq2 = sqrtf(c2);
    const float Sb  = sSb;

    // bias fragment for this thread's 8 columns
    float4 bfa = *reinterpret_cast<const float4*>(sbias + tx * 4);
    float4 bfb = *reinterpret_cast<const float4*>(sbias + 128 + tx * 4);

    #pragma unroll
    for (int i = 0; i < 8; ++i) {
        const int row = (i < 4) ? (ty * 4 + i) : (32 + ty * 4 + (i - 4));

        float g0, g1, g2, g3, g4, g5, g6, g7;
        unpack2(acc[i][0], g0, g1);
        unpack2(acc[i][1], g2, g3);
        unpack2(acc[i][2], g4, g5);
        unpack2(acc[i][3], g6, g7);

        float Sg = 0.f, dg = 0.f;
        if (tx != 0) {                        // col tx*4 == 0 only for tx==0
            Sg = fmaf(g0, g0, Sg); dg = fmaf(g0, bfa.x, dg);
        }
        Sg = fmaf(g1, g1, Sg); dg = fmaf(g1, bfa.y, dg);
        Sg = fmaf(g2, g2, Sg); dg = fmaf(g2, bfa.z, dg);
        Sg = fmaf(g3, g3, Sg); dg = fmaf(g3, bfa.w, dg);
        Sg = fmaf(g4, g4, Sg); dg = fmaf(g4, bfb.x, dg);
        Sg = fmaf(g5, g5, Sg); dg = fmaf(g5, bfb.y, dg);
        Sg = fmaf(g6, g6, Sg); dg = fmaf(g6, bfb.z, dg);
        Sg = fmaf(g7, g7, Sg); dg = fmaf(g7, bfb.w, dg);

        #pragma unroll
        for (int o = 16; o > 0; o >>= 1) {
            Sg += __shfl_xor_sync(~0u, Sg, o);
            dg += __shfl_xor_sync(~0u, dg, o);
        }

        // ---- per-row scalar chain (exact reduction of the reference) ----
        const float Sv   = svsum[row];
        const float v0p  = sqrtf(c + Sv);
        const float m    = (sqc * acoshf(fmaxf(v0p / sqc - EPSF, ACOSH_MINF)))
                           / (sqrtf(Sv) + EPSF);
        const float Sw   = m * m * Sg;
        const float dw   = m * dg;
        const float n    = sqrtf(Sw) / sqc + EPSF;
        const float ncl  = fminf(n, CLIPF);
        const float ch   = coshf(ncl);
        const float sfac = sinhf(ncl) / n;
        const float T    = sfac * sfac * Sw;
        const float hp0  = sqrtf(c + T);
        const float dd   = sqc * acoshf(fmaxf(ch, ACOSH_MINF));
        const float d2   = sqc * acoshf(fmaxf(hp0 / sqc - EPSF, ACOSH_MINF));
        const float u0   = sqc - hp0 * hp0 / sqc;
        const float suj2 = (hp0 * hp0 / c) * T;
        const float nrmu = sqrtf(suj2 - u0 * u0);
        const float mlt  = d2 / (nrmu + EPSF);
        const float alph = 1.f - mlt * (hp0 / sqc) * sfac;
        const float m2   = dw / (dd * dd);
        const float beta = alph * m2;
        const float bt0  = -(mlt * u0) * m2;
        const float btsq = bt0 * bt0 + Sb - 2.f * beta * dw + beta * beta * Sw;
        const float nb   = sqrtf(btsq) / sqc + EPSF;
        const float nbcl = fminf(nb, CLIPF);
        const float chb  = coshf(nbcl);
        const float sfb  = sinhf(nbcl) / nb;
        const float gam  = chb * sfac - sfb * beta;
        const float del  = sfb;
        const float Sbi  = gam * gam * Sw + 2.f * gam * del * dw + del * del * Sb;
        const float p0   = sqrtf(c + Sbi);
        const float d3   = sqc * acoshf(fmaxf(p0 / sqc - EPSF, ACOSH_MINF));
        const float q    = sqrtf(Sbi);
        const float mlt3 = d3 / (q + EPSF);
        const float nf   = mlt3 * q / sq2 + EPSF;
        const float nfcl = fminf(nf, CLIPF);
        const float phi  = (sinhf(nfcl) / nf) * mlt3;
        const float Aw   = phi * gam * m;
        const float Ab   = phi * del;
        const float out0 = sq2 * coshf(nfcl);

        float* orow = out + (size_t)(row0 + row) * D;
        float4 o;
        o.x = (tx == 0) ? out0 : fmaf(Aw, g0, Ab * bfa.x);
        o.y = fmaf(Aw, g1, Ab * bfa.y);
        o.z = fmaf(Aw, g2, Ab * bfa.z);
        o.w = fmaf(Aw, g3, Ab * bfa.w);
        *reinterpret_cast<float4*>(orow + tx * 4) = o;
        o.x = fmaf(Aw, g4, Ab * bfb.x);
        o.y = fmaf(Aw, g5, Ab * bfb.y);
        o.z = fmaf(Aw, g6, Ab * bfb.z);
        o.w = fmaf(Aw, g7, Ab * bfb.w);
        *reinterpret_cast<float4*>(orow + 128 + tx * 4) = o;
    }
}

extern "C" void kernel_launch(void* const* d_in, const int* in_sizes, int n_in,
                              void* d_out, int out_size)
{
    const float* V    = (const float*)d_in[0];
    const float* cin  = (const float*)d_in[1];
    const float* cout = (const float*)d_in[2];
    const float* W    = (const float*)d_in[3];
    const float* bias = (const float*)d_in[4];
    float* out = (float*)d_out;

    const int B = in_sizes[0] / D;          // 131072
    dim3 grid((B + BM - 1) / BM);           // 2048 blocks
    dh_kernel<<<grid, NT>>>(V, cin, cout, W, bias, out, B);
}

// round 4
// speedup vs baseline: 1.1740x; 1.1740x over previous
#include <cuda_runtime.h>
#include <cstdint>
#include <math.h>

// DenseHyperbolic: fused GEMM (legacy mma.sync m16n8k8 tf32, 3xTF32 split)
// + analytic per-row hyperbolic epilogue.
//   g = v'(col0=0) @ W ; out_j = Aw*g_j + Ab*bias_j ; out_0 = sqrt(c2)*cosh(.)
// tcgen05 is unreachable (harness targets plain sm_100 PTX); mma.sync is
// sm_80 PTX and lowers to fallback HMMA on sm_100.
//
// CTA: M=128 x N=256 x K=256. 512 threads = 16 warps (4M x 4N), warp tile
// 32x64. K chunked by 16 (2 k8-steps), 2-stage smem ping-pong; A staged
// LDG->regs->STS with tf32 hi/lo split on the fly, W pre-transformed into
// fragment-ordered images by a prep kernel and copied via cp.async.

constexpr int D   = 256;
constexpr int BM  = 128;
constexpr int CH  = 16;          // k per chunk
constexpr int NCH = D / CH;      // 16
constexpr int NT  = 512;
constexpr int STAGE_F = 12288;   // floats per stage: A 4096 + W 8192

#define EPSF       1e-4f
#define ACOSH_MINF 1.0001f
#define CLIPF      8.0f

// W image: [32 k8-steps][256 n][4 c] float4 = (b0h,b1h,b0l,b1l). 512 KB.
__device__ float w_img[32 * 256 * 4 * 4];

__device__ __forceinline__ float tf32r(float x) {
    uint32_t u; asm("cvt.rna.tf32.f32 %0, %1;" : "=r"(u) : "f"(x));
    return __uint_as_float(u);
}
__device__ __forceinline__ uint32_t smem_u32(const void* p) {
    uint32_t a;
    asm("{ .reg .u64 t; cvta.to.shared.u64 t, %1; cvt.u32.u64 %0, t; }"
        : "=r"(a) : "l"(p));
    return a;
}

#define MMA8(C, A, b0, b1) \
    asm volatile("mma.sync.aligned.m16n8k8.row.col.f32.tf32.tf32.f32 " \
        "{%0,%1,%2,%3}, {%4,%5,%6,%7}, {%8,%9}, {%0,%1,%2,%3};" \
        : "+f"((C)[0]), "+f"((C)[1]), "+f"((C)[2]), "+f"((C)[3]) \
        : "r"((A)[0]), "r"((A)[1]), "r"((A)[2]), "r"((A)[3]), \
          "r"(b0), "r"(b1))

#define CP_ASYNC16(dst_u32, src_ptr) \
    asm volatile("cp.async.cg.shared.global [%0], [%1], 16;" \
                 :: "r"(dst_u32), "l"(src_ptr))
#define CP_COMMIT() asm volatile("cp.async.commit_group;")
#define CP_WAIT0()  asm volatile("cp.async.wait_group 0;" ::: "memory")

// ---- prep: W -> fragment-ordered tf32 hi/lo image ----
__global__ void prep_w(const float* __restrict__ W) {
    int t = blockIdx.x * 256 + threadIdx.x;          // 32768 tasks
    int step = t >> 10, n = (t >> 2) & 255, c = t & 3;
    int k = step * 8 + c;
    float w0 = W[k * 256 + n];
    float w1 = W[(k + 4) * 256 + n];
    float h0 = tf32r(w0), l0 = tf32r(w0 - h0);
    float h1 = tf32r(w1), l1 = tf32r(w1 - h1);
    reinterpret_cast<float4*>(w_img)[(size_t)(step * 256 + n) * 4 + c] =
        make_float4(h0, h1, l0, l1);
}

// ---- main kernel ----
__global__ __launch_bounds__(NT, 1)
void dh_mma(const float* __restrict__ V,
            const float* __restrict__ cin_p,
            const float* __restrict__ cout_p,
            const float* __restrict__ bias,
            float* __restrict__ out)
{
    extern __shared__ float smem[];            // 2 stages x 48 KB
    __shared__ float sbias[256];
    __shared__ float sgp[128][4];
    __shared__ float sdgp[128][4];
    __shared__ float svsum[128];
    __shared__ float sAw[128], sAb[128], sO0[128];
    __shared__ float sred[8];
    __shared__ float sSb;

    const int tid  = threadIdx.x;
    const int lane = tid & 31;
    const int wid  = tid >> 5;
    const int wm   = wid >> 2;       // 0..3 (M)
    const int wn   = wid & 3;        // 0..3 (N)
    const int row0 = blockIdx.x * BM;

    // loader mapping
    const int lrow = tid >> 2;       // 0..127
    const int cq   = tid & 3;        // 0..3

    // bias -> smem; Sb = sum(bias^2)
    if (tid < 256) {
        float bv = (tid == 0) ? 0.f : __ldg(&bias[tid - 1]);
        sbias[tid] = bv;
        float sq = bv * bv;
        #pragma unroll
        for (int o = 16; o > 0; o >>= 1) sq += __shfl_xor_sync(~0u, sq, o);
        if (lane == 0) sred[wid] = sq;
    }

    float svloc = 0.f;

    // A loader: LDG chunk i into regs, tf32 hi/lo split -> two float4s
    auto load_a = [&](int i, float4& s0v, float4& s1v) {
        const float* base = V + (size_t)(row0 + lrow) * D + i * CH;
        float v0 = base[cq];
        float v1 = base[cq + 4];
        float v2 = base[cq + 8];
        float v3 = base[cq + 12];
        if (i == 0 && cq == 0) v0 = 0.f;        // zero time coordinate k=0
        svloc += v0 * v0 + v1 * v1 + v2 * v2 + v3 * v3;
        float h0 = tf32r(v0), h1 = tf32r(v1), h2 = tf32r(v2), h3 = tf32r(v3);
        s0v = make_float4(h0, h1, tf32r(v0 - h0), tf32r(v1 - h1));
        s1v = make_float4(h2, h3, tf32r(v2 - h2), tf32r(v3 - h3));
    };
    auto sts_a = [&](float* stA, const float4& s0v, const float4& s1v) {
        // A_s[s][row][c] float4; float4 index for s=0 is row*4+c == tid
        reinterpret_cast<float4*>(stA)[tid]       = s0v;
        reinterpret_cast<float4*>(stA)[512 + tid] = s1v;
    };
    auto cp_w = [&](int i, float* stW) {
        const float* src = w_img + (size_t)i * 8192;
        #pragma unroll
        for (int j = 0; j < 4; ++j) {
            int fidx = tid + j * 512;               // float4 index
            CP_ASYNC16(smem_u32(stW + fidx * 4), src + fidx * 4);
        }
        CP_COMMIT();
    };

    // prologue: fill stage 0 with chunk 0
    {
        float4 s0v, s1v;
        load_a(0, s0v, s1v);
        cp_w(0, smem + 4096);
        sts_a(smem, s0v, s1v);
        CP_WAIT0();
        __syncthreads();
    }
    if (tid == 0) {
        float s = 0.f;
        #pragma unroll
        for (int i = 0; i < 8; i++) s += sred[i];
        sSb = s;
    }

    float acc[2][8][4];
    #pragma unroll
    for (int mt = 0; mt < 2; ++mt)
        #pragma unroll
        for (int nt = 0; nt < 8; ++nt)
            #pragma unroll
            for (int e = 0; e < 4; ++e) acc[mt][nt][e] = 0.f;

    int st = 0;
    for (int i = 0; i < NCH; ++i) {
        float* stA = smem + st * STAGE_F;
        float* stW = stA + 4096;
        float* nxA = smem + (st ^ 1) * STAGE_F;
        float* nxW = nxA + 4096;

        float4 s0v, s1v;
        const bool more = (i + 1 < NCH);
        if (more) {
            load_a(i + 1, s0v, s1v);     // LDGs in flight across MMA phase
            cp_w(i + 1, nxW);
        }

        #pragma unroll
        for (int s = 0; s < 2; ++s) {
            uint32_t ah[2][4], al[2][4];
            #pragma unroll
            for (int mt = 0; mt < 2; ++mt) {
                int rb = wm * 32 + mt * 16 + (lane >> 2);
                uint4 q0 = reinterpret_cast<const uint4*>(stA)
                               [(s * 128 + rb) * 4 + (lane & 3)];
                uint4 q1 = reinterpret_cast<const uint4*>(stA)
                               [(s * 128 + rb + 8) * 4 + (lane & 3)];
                ah[mt][0] = q0.x; ah[mt][2] = q0.y;
                al[mt][0] = q0.z; al[mt][2] = q0.w;
                ah[mt][1] = q1.x; ah[mt][3] = q1.y;
                al[mt][1] = q1.z; al[mt][3] = q1.w;
            }
            #pragma unroll
            for (int nt = 0; nt < 8; ++nt) {
                int nn = wn * 64 + nt * 8 + (lane >> 2);
                uint4 qb = reinterpret_cast<const uint4*>(stW)
                               [(s * 256 + nn) * 4 + (lane & 3)];
                #pragma unroll
                for (int mt = 0; mt < 2; ++mt) {
                    MMA8(acc[mt][nt], ah[mt], qb.x, qb.y);   // hi*hi
                    MMA8(acc[mt][nt], ah[mt], qb.z, qb.w);   // hi*lo
                    MMA8(acc[mt][nt], al[mt], qb.x, qb.y);   // lo*hi
                }
            }
        }

        if (more) {
            sts_a(nxA, s0v, s1v);
            CP_WAIT0();
        }
        __syncthreads();
        st ^= 1;
    }

    // Sv: lanes sharing lrow differ in cq only (xor 1,2)
    svloc += __shfl_xor_sync(~0u, svloc, 1);
    svloc += __shfl_xor_sync(~0u, svloc, 2);
    if (cq == 0) svsum[lrow] = svloc;

    // per-thread partial Sg/dg over its 16 columns x 4 rows
    float psg[4] = {0.f, 0.f, 0.f, 0.f};
    float pdg[4] = {0.f, 0.f, 0.f, 0.f};
    #pragma unroll
    for (int nt = 0; nt < 8; ++nt) {
        float2 bf = *reinterpret_cast<const float2*>(
            &sbias[wn * 64 + nt * 8 + 2 * (lane & 3)]);
        #pragma unroll
        for (int mt = 0; mt < 2; ++mt) {
            const float* C = acc[mt][nt];
            bool isc0 = (wn == 0 && nt == 0 && (lane & 3) == 0);
            if (!isc0) {
                psg[mt * 2]     = fmaf(C[0], C[0], psg[mt * 2]);
                pdg[mt * 2]     = fmaf(C[0], bf.x, pdg[mt * 2]);
                psg[mt * 2 + 1] = fmaf(C[2], C[2], psg[mt * 2 + 1]);
                pdg[mt * 2 + 1] = fmaf(C[2], bf.x, pdg[mt * 2 + 1]);
            } else {
                // col0 excluded for rows r and r+8 of mt=0
                psg[1] = fmaf(C[2], C[2], psg[1]);  // wait: C[2] is row r+8 col0 -> also excluded
                psg[1] = fmaf(-C[2], C[2], psg[1]); // undo (keep excluded)
            }
            psg[mt * 2]     = fmaf(C[1], C[1], psg[mt * 2]);
            pdg[mt * 2]     = fmaf(C[1], bf.y, pdg[mt * 2]);
            psg[mt * 2 + 1] = fmaf(C[3], C[3], psg[mt * 2 + 1]);
            pdg[mt * 2 + 1] = fmaf(C[3], bf.y, pdg[mt * 2 + 1]);
        }
    }
    #pragma unroll
    for (int e = 0; e < 4; ++e) {
        psg[e] += __shfl_xor_sync(~0u, psg[e], 1);
        psg[e] += __shfl_xor_sync(~0u, psg[e], 2);
        pdg[e] += __shfl_xor_sync(~0u, pdg[e], 1);
        pdg[e] += __shfl_xor_sync(~0u, pdg[e], 2);
    }
    if ((lane & 3) == 0) {
        int r0 = wm * 32 + (lane >> 2);
        sgp[r0][wn]      = psg[0];  sdgp[r0][wn]      = pdg[0];
        sgp[r0 + 8][wn]  = psg[1];  sdgp[r0 + 8][wn]  = pdg[1];
        sgp[r0 + 16][wn] = psg[2];  sdgp[r0 + 16][wn] = pdg[2];
        sgp[r0 + 24][wn] = psg[3];  sdgp[r0 + 24][wn] = pdg[3];
    }
    __syncthreads();

    if (tid < 128) {
        float Sg = sgp[tid][0] + sgp[tid][1] + sgp[tid][2] + sgp[tid][3];
        float dg = sdgp[tid][0] + sdgp[tid][1] + sdgp[tid][2] + sdgp[tid][3];

        const float c   = *cin_p;
        const float c2  = *cout_p;
        const float sqc = sqrtf(c);
        const float sq2 = sqrtf(c2);
        const float Sb  = sSb;
        const float Sv  = svsum[tid];

        const float v0p  = sqrtf(c + Sv);
        const float m    = (sqc * acoshf(fmaxf(v0p / sqc - EPSF, ACOSH_MINF)))
                           / (sqrtf(Sv) + EPSF);
        const float Sw   = m * m * Sg;
        const float dw   = m * dg;
        const float n    = sqrtf(Sw) / sqc + EPSF;
        const float ncl  = fminf(n, CLIPF);
        const float ch   = coshf(ncl);
        const float sfac = sinhf(ncl) / n;
        const float T    = sfac * sfac * Sw;
        const float hp0  = sqrtf(c + T);
        const float dd   = sqc * acoshf(fmaxf(ch, ACOSH_MINF));
        const float d2   = sqc * acoshf(fmaxf(hp0 / sqc - EPSF, ACOSH_MINF));
        const float u0   = sqc - hp0 * hp0 / sqc;
        const float suj2 = (hp0 * hp0 / c) * T;
        const float nrmu = sqrtf(suj2 - u0 * u0);
        const float mlt  = d2 / (nrmu + EPSF);
        const float alph = 1.f - mlt * (hp0 / sqc) * sfac;
        const float m2   = dw / (dd * dd);
        const float beta = alph * m2;
        const float bt0  = -(mlt * u0) * m2;
        const float btsq = bt0 * bt0 + Sb - 2.f * beta * dw + beta * beta * Sw;
        const float nb   = sqrtf(btsq) / sqc + EPSF;
        const float nbcl = fminf(nb, CLIPF);
        const float chb  = coshf(nbcl);
        const float sfb  = sinhf(nbcl) / nb;
        const float gam  = chb * sfac - sfb * beta;
        const float del  = sfb;
        const float Sbi  = gam * gam * Sw + 2.f * gam * del * dw + del * del * Sb;
        const float p0   = sqrtf(c + Sbi);
        const float d3   = sqc * acoshf(fmaxf(p0 / sqc - EPSF, ACOSH_MINF));
        const float q    = sqrtf(Sbi);
        const float mlt3 = d3 / (q + EPSF);
        const float nf   = mlt3 * q / sq2 + EPSF;
        const float nfcl = fminf(nf, CLIPF);
        const float phi  = (sinhf(nfcl) / nf) * mlt3;
        sAw[tid] = phi * gam * m;
        sAb[tid] = phi * del;
        sO0[tid] = sq2 * coshf(nfcl);
    }
    __syncthreads();

    // stores: 2 cols x 4 rows per (nt)
    #pragma unroll
    for (int mt = 0; mt < 2; ++mt) {
        #pragma unroll
        for (int rp = 0; rp < 2; ++rp) {
            int r = wm * 32 + mt * 16 + rp * 8 + (lane >> 2);
            float Aw = sAw[r], Ab = sAb[r];
            float* orow = out + (size_t)(row0 + r) * D;
            #pragma unroll
            for (int nt = 0; nt < 8; ++nt) {
                float2 bf = *reinterpret_cast<const float2*>(
                    &sbias[wn * 64 + nt * 8 + 2 * (lane & 3)]);
                float g0 = acc[mt][nt][rp * 2];
                float g1 = acc[mt][nt][rp * 2 + 1];
                float2 o;
                o.x = fmaf(Aw, g0, Ab * bf.x);
                o.y = fmaf(Aw, g1, Ab * bf.y);
                if (wn == 0 && nt == 0 && (lane & 3) == 0) o.x = sO0[r];
                *reinterpret_cast<float2*>(
                    orow + wn * 64 + nt * 8 + 2 * (lane & 3)) = o;
            }
        }
    }
}

extern "C" void kernel_launch(void* const* d_in, const int* in_sizes, int n_in,
                              void* d_out, int out_size)
{
    const float* V    = (const float*)d_in[0];
    const float* cin  = (const float*)d_in[1];
    const float* cout = (const float*)d_in[2];
    const float* W    = (const float*)d_in[3];
    const float* bias = (const float*)d_in[4];
    float* out = (float*)d_out;

    const int nrow = in_sizes[0] / D;            // 131072
    const int smem = 2 * STAGE_F * 4;            // 96 KB dynamic

    cudaFuncSetAttribute(dh_mma, cudaFuncAttributeMaxDynamicSharedMemorySize, smem);

    prep_w<<<128, 256>>>(W);
    dh_mma<<<nrow / BM, NT, smem>>>(V, cin, cout, bias, out);
}

// round 5
// speedup vs baseline: 2.2641x; 1.9285x over previous
#include <cuda_runtime.h>
#include <cuda_fp16.h>
#include <cstdint>
#include <math.h>

// DenseHyperbolic: fused GEMM (mma.sync m16n8k16 fp16, Markidis fp16x3 split,
// fp32 accumulate) + analytic per-row hyperbolic epilogue.
//   g = v'(col0=0) @ W ; out_j = Aw*g_j + Ab*bias_j ; out_0 = sqrt(c2)*cosh(.)
// fp16 legacy tensor path = 2x tf32 rate; ldmatrix from 128B-contiguous 8x8
// tiles removes indexed-LDS ALU overhead (R4: alu pipe 40.8%).
//
// CTA: M=128 x N=256 x K=256, 512 threads = 16 warps (4M x 4N), warp tile
// 32x64. K chunked by 16; 2-stage ping-pong. A: LDG->regs->(hi/lo fp16)->STS
// by threads 0-255. W: pre-tiled fragment-order image (prep kernel), copied
// with cp.async by threads 256-511.

constexpr int D   = 256;
constexpr int BM  = 128;
constexpr int NCH = 16;            // chunks of K=16
constexpr int NT  = 512;
constexpr int STAGE_B = 24576;     // bytes/stage: AH 4K | AL 4K | WH 8K | WL 8K

#define EPSF       1e-4f
#define ACOSH_MINF 1.0001f
#define CLIPF      8.0f

// W image: [16 chunks][ WH: 64 tiles(128B) | WL: 64 tiles ] = 256 KB.
// tile index = ntile*2 + ktile; tile = 8 rows(n) x 8 cols(k) fp16.
__device__ __half w_img[16 * 8192];

__device__ __forceinline__ uint32_t smem_u32(const void* p) {
    uint32_t a;
    asm("{ .reg .u64 t; cvta.to.shared.u64 t, %1; cvt.u32.u64 %0, t; }"
        : "=r"(a) : "l"(p));
    return a;
}
__device__ __forceinline__ uint32_t packh(__half a, __half b) {
    __half2 h = __halves2half2(a, b);
    return *reinterpret_cast<uint32_t*>(&h);
}

#define MMAF16(C, A, b0, b1) \
    asm volatile("mma.sync.aligned.m16n8k16.row.col.f32.f16.f16.f32 " \
        "{%0,%1,%2,%3}, {%4,%5,%6,%7}, {%8,%9}, {%0,%1,%2,%3};" \
        : "+f"((C)[0]), "+f"((C)[1]), "+f"((C)[2]), "+f"((C)[3]) \
        : "r"((A)[0]), "r"((A)[1]), "r"((A)[2]), "r"((A)[3]), \
          "r"(b0), "r"(b1))

#define LDSM4(R, addr) \
    asm volatile("ldmatrix.sync.aligned.m8n8.x4.shared.b16 {%0,%1,%2,%3}, [%4];" \
        : "=r"((R)[0]), "=r"((R)[1]), "=r"((R)[2]), "=r"((R)[3]) : "r"(addr))
#define LDSM2(r0, r1, addr) \
    asm volatile("ldmatrix.sync.aligned.m8n8.x2.shared.b16 {%0,%1}, [%2];" \
        : "=r"(r0), "=r"(r1) : "r"(addr))

#define CP_ASYNC16(dst_u32, src_ptr) \
    asm volatile("cp.async.cg.shared.global [%0], [%1], 16;" \
                 :: "r"(dst_u32), "l"(src_ptr))
#define CP_COMMIT() asm volatile("cp.async.commit_group;")
#define CP_WAIT0()  asm volatile("cp.async.wait_group 0;" ::: "memory")

// ---- prep: W -> fragment-tiled fp16 hi/lo image. W is [k][n] row-major. ----
__global__ void prep_w(const float* __restrict__ W) {
    int t = blockIdx.x * 256 + threadIdx.x;      // 8192 tasks
    int c  = t >> 9;
    int rm = t & 511;
    int ntile = rm >> 4;
    int kt = (rm >> 3) & 1;
    int rr = rm & 7;                             // n within tile
    int n  = ntile * 8 + rr;
    int kb = c * 16 + kt * 8;
    __half h[8], l[8];
    #pragma unroll
    for (int j = 0; j < 8; ++j) {
        float v  = W[(size_t)(kb + j) * 256 + n];
        __half hi = __float2half_rn(v);
        h[j] = hi;
        l[j] = __float2half_rn(v - __half2float(hi));
    }
    size_t base = (size_t)c * 8192 + (ntile * 2 + kt) * 64 + rr * 8;  // halves
    *reinterpret_cast<uint4*>(w_img + base)        = *reinterpret_cast<const uint4*>(h);
    *reinterpret_cast<uint4*>(w_img + base + 4096) = *reinterpret_cast<const uint4*>(l);
}

// ---- main kernel ----
__global__ __launch_bounds__(NT, 1)
void dh_mma(const float* __restrict__ V,
            const float* __restrict__ cin_p,
            const float* __restrict__ cout_p,
            const float* __restrict__ bias,
            float* __restrict__ out)
{
    extern __shared__ __align__(16) char smc[];          // 2 x 24 KB
    __shared__ float sbias[256];
    __shared__ float sgp[128][4];
    __shared__ float sdgp[128][4];
    __shared__ float svsum[128];
    __shared__ float sAw[128], sAb[128], sO0[128];
    __shared__ float sred[8];
    __shared__ float sSb;

    const int tid  = threadIdx.x;
    const int lane = tid & 31;
    const int wid  = tid >> 5;
    const int wm   = wid >> 2;        // 0..3 (M)
    const int wn   = wid & 3;         // 0..3 (N)
    const int row0 = blockIdx.x * BM;
    const uint32_t smem0 = smem_u32(smc);

    // bias -> smem; Sb = sum(bias^2)
    if (tid < 256) {
        float bv = (tid == 0) ? 0.f : __ldg(&bias[tid - 1]);
        sbias[tid] = bv;
        float sq = bv * bv;
        #pragma unroll
        for (int o = 16; o > 0; o >>= 1) sq += __shfl_xor_sync(~0u, sq, o);
        if (lane == 0) sred[wid] = sq;
    }

    // ---- A loader state (threads 0..255): row r = tid>>1, half kt = tid&1 ----
    const int lr  = tid >> 1;
    const int lkt = tid & 1;
    const uint32_t aStsOff = (uint32_t)(((lr >> 3) * 2 + lkt) * 128 + (lr & 7) * 16);
    float svloc = 0.f;
    float4 xA, yA;                    // pending raw A (8 floats)

    auto load_a = [&](int i) {
        const float4* p = reinterpret_cast<const float4*>(
            V + (size_t)(row0 + lr) * D + i * 16 + lkt * 8);
        xA = p[0]; yA = p[1];
        if (i == 0 && lkt == 0) xA.x = 0.f;       // zero time coordinate
        svloc += xA.x * xA.x + xA.y * xA.y + xA.z * xA.z + xA.w * xA.w
               + yA.x * yA.x + yA.y * yA.y + yA.z * yA.z + yA.w * yA.w;
    };
    auto sts_a = [&](int stg) {
        float vs[8] = {xA.x, xA.y, xA.z, xA.w, yA.x, yA.y, yA.z, yA.w};
        uint32_t H[4], L[4];
        #pragma unroll
        for (int j = 0; j < 4; ++j) {
            __half h0 = __float2half_rn(vs[2 * j]);
            __half h1 = __float2half_rn(vs[2 * j + 1]);
            __half l0 = __float2half_rn(vs[2 * j]     - __half2float(h0));
            __half l1 = __float2half_rn(vs[2 * j + 1] - __half2float(h1));
            H[j] = packh(h0, h1);
            L[j] = packh(l0, l1);
        }
        char* dst = smc + stg * STAGE_B + aStsOff;
        *reinterpret_cast<uint4*>(dst)        = *reinterpret_cast<const uint4*>(H);
        *reinterpret_cast<uint4*>(dst + 4096) = *reinterpret_cast<const uint4*>(L);
    };
    auto cp_w = [&](int i, int stg) {            // threads 256..511
        const __half* src = w_img + (size_t)i * 8192;
        uint32_t dst = smem0 + stg * STAGE_B + 8192;
        int m = tid - 256;
        #pragma unroll
        for (int j = 0; j < 4; ++j) {
            int f = m + j * 256;                 // 16B units, 0..1023
            CP_ASYNC16(dst + f * 16, src + f * 8);
        }
        CP_COMMIT();
    };

    // ldmatrix lane offsets
    uint32_t aoff[2];
    {
        int m = lane >> 3;
        int tsel = ((m & 1) << 1) | (m >> 1);    // matrix -> tile offset {0,2,1,3}
        #pragma unroll
        for (int mt = 0; mt < 2; ++mt) {
            int rtm = wm * 4 + mt * 2;
            aoff[mt] = (uint32_t)((rtm * 2 + tsel) * 128 + (lane & 7) * 16);
        }
    }
    const uint32_t boff = (uint32_t)((wn * 8) * 256
                        + (((lane & 15) >> 3) * 128) + (lane & 7) * 16);

    // ---- prologue: stage 0 = chunk 0 ----
    if (tid < 256) load_a(0); else cp_w(0, 0);
    if (tid < 256) sts_a(0);
    CP_WAIT0();
    __syncthreads();
    if (tid == 0) {
        float s = 0.f;
        #pragma unroll
        for (int i = 0; i < 8; i++) s += sred[i];
        sSb = s;
    }

    float acc[2][8][4];
    #pragma unroll
    for (int mt = 0; mt < 2; ++mt)
        #pragma unroll
        for (int nt = 0; nt < 8; ++nt)
            #pragma unroll
            for (int e = 0; e < 4; ++e) acc[mt][nt][e] = 0.f;

    int st = 0;
    for (int i = 0; i < NCH; ++i) {
        const bool more = (i + 1 < NCH);
        if (more) {
            if (tid < 256) load_a(i + 1);
            else           cp_w(i + 1, st ^ 1);
        }

        // ---- MMA on stage st ----
        const uint32_t sb = smem0 + st * STAGE_B;
        uint32_t ah[2][4], al[2][4];
        #pragma unroll
        for (int mt = 0; mt < 2; ++mt) {
            LDSM4(ah[mt], sb + aoff[mt]);
            LDSM4(al[mt], sb + 4096 + aoff[mt]);
        }
        const uint32_t wb = sb + 8192 + boff;
        #pragma unroll
        for (int nt = 0; nt < 8; ++nt) {
            uint32_t bh0, bh1, bl0, bl1;
            LDSM2(bh0, bh1, wb + nt * 256);
            LDSM2(bl0, bl1, wb + 8192 + nt * 256);
            #pragma unroll
            for (int mt = 0; mt < 2; ++mt) {
                MMAF16(acc[mt][nt], ah[mt], bh0, bh1);   // hi*hi
                MMAF16(acc[mt][nt], ah[mt], bl0, bl1);   // hi*lo
                MMAF16(acc[mt][nt], al[mt], bh0, bh1);   // lo*hi
            }
        }

        if (more) {
            if (tid < 256) sts_a(st ^ 1);
            CP_WAIT0();
        }
        __syncthreads();
        st ^= 1;
    }

    // Sv: pair (lkt 0/1) shares row; adjacent lanes.
    if (tid < 256) {
        float v = svloc + __shfl_xor_sync(~0u, svloc, 1);
        if (lkt == 0) svsum[lr] = v;
    }

    // per-thread partial Sg/dg over its 16 columns x 4 rows
    float psg[4] = {0.f, 0.f, 0.f, 0.f};
    float pdg[4] = {0.f, 0.f, 0.f, 0.f};
    const bool isc0 = (wn == 0 && (lane & 3) == 0);   // col0 owner when nt==0
    #pragma unroll
    for (int nt = 0; nt < 8; ++nt) {
        float2 bf = *reinterpret_cast<const float2*>(
            &sbias[wn * 64 + nt * 8 + 2 * (lane & 3)]);
        #pragma unroll
        for (int mt = 0; mt < 2; ++mt) {
            const float* C = acc[mt][nt];
            if (!(isc0 && nt == 0)) {             // exclude column 0 (rows r, r+8)
                psg[mt * 2]     = fmaf(C[0], C[0], psg[mt * 2]);
                pdg[mt * 2]     = fmaf(C[0], bf.x, pdg[mt * 2]);
                psg[mt * 2 + 1] = fmaf(C[2], C[2], psg[mt * 2 + 1]);
                pdg[mt * 2 + 1] = fmaf(C[2], bf.x, pdg[mt * 2 + 1]);
            }
            psg[mt * 2]     = fmaf(C[1], C[1], psg[mt * 2]);
            pdg[mt * 2]     = fmaf(C[1], bf.y, pdg[mt * 2]);
            psg[mt * 2 + 1] = fmaf(C[3], C[3], psg[mt * 2 + 1]);
            pdg[mt * 2 + 1] = fmaf(C[3], bf.y, pdg[mt * 2 + 1]);
        }
    }
    #pragma unroll
    for (int e = 0; e < 4; ++e) {
        psg[e] += __shfl_xor_sync(~0u, psg[e], 1);
        psg[e] += __shfl_xor_sync(~0u, psg[e], 2);
        pdg[e] += __shfl_xor_sync(~0u, pdg[e], 1);
        pdg[e] += __shfl_xor_sync(~0u, pdg[e], 2);
    }
    if ((lane & 3) == 0) {
        int r0 = wm * 32 + (lane >> 2);
        sgp[r0][wn]      = psg[0];  sdgp[r0][wn]      = pdg[0];
        sgp[r0 + 8][wn]  = psg[1];  sdgp[r0 + 8][wn]  = pdg[1];
        sgp[r0 + 16][wn] = psg[2];  sdgp[r0 + 16][wn] = pdg[2];
        sgp[r0 + 24][wn] = psg[3];  sdgp[r0 + 24][wn] = pdg[3];
    }
    __syncthreads();

    if (tid < 128) {
        float Sg = sgp[tid][0] + sgp[tid][1] + sgp[tid][2] + sgp[tid][3];
        float dg = sdgp[tid][0] + sdgp[tid][1] + sdgp[tid][2] + sdgp[tid][3];

        const float c   = *cin_p;
        const float c2  = *cout_p;
        const float sqc = sqrtf(c);
        const float sq2 = sqrtf(c2);
        const float Sb  = sSb;
        const float Sv  = svsum[tid];

        const float v0p  = sqrtf(c + Sv);
        const float m    = (sqc * acoshf(fmaxf(v0p / sqc - EPSF, ACOSH_MINF)))
                           / (sqrtf(Sv) + EPSF);
        const float Sw   = m * m * Sg;
        const float dw   = m * dg;
        const float n    = sqrtf(Sw) / sqc + EPSF;
        const float ncl  = fminf(n, CLIPF);
        const float ch   = coshf(ncl);
        const float sfac = sinhf(ncl) / n;
        const float T    = sfac * sfac * Sw;
        const float hp0  = sqrtf(c + T);
        const float dd   = sqc * acoshf(fmaxf(ch, ACOSH_MINF));
        const float d2   = sqc * acoshf(fmaxf(hp0 / sqc - EPSF, ACOSH_MINF));
        const float u0   = sqc - hp0 * hp0 / sqc;
        const float suj2 = (hp0 * hp0 / c) * T;
        const float nrmu = sqrtf(suj2 - u0 * u0);
        const float mlt  = d2 / (nrmu + EPSF);
        const float alph = 1.f - mlt * (hp0 / sqc) * sfac;
        const float m2   = dw / (dd * dd);
        const float beta = alph * m2;
        const float bt0  = -(mlt * u0) * m2;
        const float btsq = bt0 * bt0 + Sb - 2.f * beta * dw + beta * beta * Sw;
        const float nb   = sqrtf(btsq) / sqc + EPSF;
        const float nbcl = fminf(nb, CLIPF);
        const float chb  = coshf(nbcl);
        const float sfb  = sinhf(nbcl) / nb;
        const float gam  = chb * sfac - sfb * beta;
        const float del  = sfb;
        const float Sbi  = gam * gam * Sw + 2.f * gam * del * dw + del * del * Sb;
        const float p0   = sqrtf(c + Sbi);
        const float d3   = sqc * acoshf(fmaxf(p0 / sqc - EPSF, ACOSH_MINF));
        const float q    = sqrtf(Sbi);
        const float mlt3 = d3 / (q + EPSF);
        const float nf   = mlt3 * q / sq2 + EPSF;
        const float nfcl = fminf(nf, CLIPF);
        const float phi  = (sinhf(nfcl) / nf) * mlt3;
        sAw[tid] = phi * gam * m;
        sAb[tid] = phi * del;
        sO0[tid] = sq2 * coshf(nfcl);
    }
    __syncthreads();

    // stores
    #pragma unroll
    for (int mt = 0; mt < 2; ++mt) {
        #pragma unroll
        for (int rp = 0; rp < 2; ++rp) {
            int r = wm * 32 + mt * 16 + rp * 8 + (lane >> 2);
            float Aw = sAw[r], Ab = sAb[r];
            float* orow = out + (size_t)(row0 + r) * D;
            #pragma unroll
            for (int nt = 0; nt < 8; ++nt) {
                float2 bf = *reinterpret_cast<const float2*>(
                    &sbias[wn * 64 + nt * 8 + 2 * (lane & 3)]);
                float g0 = acc[mt][nt][rp * 2];
                float g1 = acc[mt][nt][rp * 2 + 1];
                float2 o;
                o.x = fmaf(Aw, g0, Ab * bf.x);
                o.y = fmaf(Aw, g1, Ab * bf.y);
                if (wn == 0 && nt == 0 && (lane & 3) == 0) o.x = sO0[r];
                *reinterpret_cast<float2*>(
                    orow + wn * 64 + nt * 8 + 2 * (lane & 3)) = o;
            }
        }
    }
}

extern "C" void kernel_launch(void* const* d_in, const int* in_sizes, int n_in,
                              void* d_out, int out_size)
{
    const float* V    = (const float*)d_in[0];
    const float* cin  = (const float*)d_in[1];
    const float* cout = (const float*)d_in[2];
    const float* W    = (const float*)d_in[3];
    const float* bias = (const float*)d_in[4];
    float* out = (float*)d_out;

    const int nrow = in_sizes[0] / D;             // 131072
    const int smem = 2 * STAGE_B;                 // 48 KB dynamic

    cudaFuncSetAttribute(dh_mma, cudaFuncAttributeMaxDynamicSharedMemorySize, smem);

    prep_w<<<32, 256>>>(W);
    dh_mma<<<nrow / BM, NT, smem>>>(V, cin, cout, bias, out);
}

// round 6
// speedup vs baseline: 2.4583x; 1.0858x over previous
#include <cuda_runtime.h>
#include <cuda_fp16.h>
#include <cstdint>
#include <math.h>

// DenseHyperbolic: fused GEMM (mma.sync m16n8k16 fp16, Markidis fp16x3 split,
// fp32 accumulate) + analytic per-row hyperbolic epilogue.
//   g = v'(col0=0) @ W ; out_j = Aw*g_j + Ab*bias_j ; out_0 = sqrt(c2)*cosh(.)
//
// R5 was utilization-bound: tensor 44%, one 512-thread CTA/SM convoying on
// __syncthreads every chunk. R6: BM=64 / 256 threads / 2 CTAs per SM -> the
// two CTAs barrier independently and hide each other's pipeline tails.
// W image re-tiled so hi/lo k0/k1 tiles per nt are adjacent: one LDSM4 per nt.
//
// CTA: M=64 x N=256 x K=256, 8 warps (2M x 4N), warp tile 32x64. K chunked
// by 16; 2-stage ping-pong (20 KB/stage). A: LDG->regs->(hi/lo fp16)->STS.
// W: pre-tiled fragment-order image (prep kernel), cp.async.

constexpr int D   = 256;
constexpr int BM  = 64;
constexpr int NCH = 16;            // chunks of K=16
constexpr int NT  = 256;
constexpr int STAGE_B = 20480;     // bytes/stage: AH 2K | AL 2K | W 16K

#define EPSF       1e-4f
#define ACOSH_MINF 1.0001f
#define CLIPF      8.0f

// W image: [16 chunks][32 ngroups][4 tiles: hiK0|hiK1|loK0|loK1][64 halves]
__device__ __half w_img[16 * 8192];

__device__ __forceinline__ uint32_t smem_u32(const void* p) {
    uint32_t a;
    asm("{ .reg .u64 t; cvta.to.shared.u64 t, %1; cvt.u32.u64 %0, t; }"
        : "=r"(a) : "l"(p));
    return a;
}
__device__ __forceinline__ uint32_t packh(__half a, __half b) {
    __half2 h = __halves2half2(a, b);
    return *reinterpret_cast<uint32_t*>(&h);
}

#define MMAF16(C, A, b0, b1) \
    asm volatile("mma.sync.aligned.m16n8k16.row.col.f32.f16.f16.f32 " \
        "{%0,%1,%2,%3}, {%4,%5,%6,%7}, {%8,%9}, {%0,%1,%2,%3};" \
        : "+f"((C)[0]), "+f"((C)[1]), "+f"((C)[2]), "+f"((C)[3]) \
        : "r"((A)[0]), "r"((A)[1]), "r"((A)[2]), "r"((A)[3]), \
          "r"(b0), "r"(b1))

#define LDSM4(R, addr) \
    asm volatile("ldmatrix.sync.aligned.m8n8.x4.shared.b16 {%0,%1,%2,%3}, [%4];" \
        : "=r"((R)[0]), "=r"((R)[1]), "=r"((R)[2]), "=r"((R)[3]) : "r"(addr))

#define CP_ASYNC16(dst_u32, src_ptr) \
    asm volatile("cp.async.cg.shared.global [%0], [%1], 16;" \
                 :: "r"(dst_u32), "l"(src_ptr))
#define CP_COMMIT() asm volatile("cp.async.commit_group;")
#define CP_WAIT0()  asm volatile("cp.async.wait_group 0;" ::: "memory")

// ---- prep: W[k][n] row-major -> fragment-tiled fp16 hi/lo image ----
__global__ void prep_w(const float* __restrict__ W) {
    int t = blockIdx.x * 256 + threadIdx.x;      // 8192 tasks
    int c  = t >> 9;
    int rm = t & 511;
    int ng = rm >> 4;                            // n group (8 cols)
    int kt = (rm >> 3) & 1;
    int rr = rm & 7;                             // n within group
    int n  = ng * 8 + rr;
    int kb = c * 16 + kt * 8;
    __half h[8], l[8];
    #pragma unroll
    for (int j = 0; j < 8; ++j) {
        float v  = W[(size_t)(kb + j) * 256 + n];
        __half hi = __float2half_rn(v);
        h[j] = hi;
        l[j] = __float2half_rn(v - __half2float(hi));
    }
    size_t base = (size_t)c * 8192 + ng * 256 + kt * 64 + rr * 8;   // halves
    *reinterpret_cast<uint4*>(w_img + base)       = *reinterpret_cast<const uint4*>(h);
    *reinterpret_cast<uint4*>(w_img + base + 128) = *reinterpret_cast<const uint4*>(l);
}

// ---- main kernel ----
__global__ __launch_bounds__(NT, 2)
void dh_mma(const float* __restrict__ V,
            const float* __restrict__ cin_p,
            const float* __restrict__ cout_p,
            const float* __restrict__ bias,
            float* __restrict__ out)
{
    extern __shared__ __align__(16) char smc[];          // 2 x 20 KB
    __shared__ float sbias[256];
    __shared__ float sgp[64][4];
    __shared__ float sdgp[64][4];
    __shared__ float svsum[64];
    __shared__ float sAw[64], sAb[64], sO0[64];
    __shared__ float sred[8];
    __shared__ float sSb;

    const int tid  = threadIdx.x;
    const int lane = tid & 31;
    const int wid  = tid >> 5;
    const int wm   = wid >> 2;        // 0..1 (M)
    const int wn   = wid & 3;         // 0..3 (N)
    const int row0 = blockIdx.x * BM;
    const uint32_t smem0 = smem_u32(smc);

    // bias -> smem; Sb = sum(bias^2)
    {
        float bv = (tid == 0) ? 0.f : __ldg(&bias[tid - 1]);
        sbias[tid] = bv;
        float sq = bv * bv;
        #pragma unroll
        for (int o = 16; o > 0; o >>= 1) sq += __shfl_xor_sync(~0u, sq, o);
        if (lane == 0) sred[wid] = sq;
    }

    // ---- A loader: row lr = tid>>2, float4 slot q = tid&3 ----
    const int lr = tid >> 2;
    const int q  = tid & 3;
    const uint32_t aStsOff = (uint32_t)(((lr >> 3) * 2 + (q >> 1)) * 128
                                        + (lr & 7) * 16 + (q & 1) * 8);
    float svloc = 0.f;
    float4 xA;                         // pending raw A (4 floats)

    auto load_a = [&](int i) {
        xA = *reinterpret_cast<const float4*>(
            V + (size_t)(row0 + lr) * D + i * 16 + q * 4);
        if (i == 0 && q == 0) xA.x = 0.f;        // zero time coordinate
        svloc += xA.x * xA.x + xA.y * xA.y + xA.z * xA.z + xA.w * xA.w;
    };
    auto sts_a = [&](int stg) {
        __half h0 = __float2half_rn(xA.x), h1 = __float2half_rn(xA.y);
        __half h2 = __float2half_rn(xA.z), h3 = __float2half_rn(xA.w);
        __half l0 = __float2half_rn(xA.x - __half2float(h0));
        __half l1 = __float2half_rn(xA.y - __half2float(h1));
        __half l2 = __float2half_rn(xA.z - __half2float(h2));
        __half l3 = __float2half_rn(xA.w - __half2float(h3));
        char* dst = smc + stg * STAGE_B + aStsOff;
        *reinterpret_cast<uint2*>(dst) = make_uint2(packh(h0, h1), packh(h2, h3));
        *reinterpret_cast<uint2*>(dst + 2048) = make_uint2(packh(l0, l1), packh(l2, l3));
    };
    auto cp_w = [&](int i, int stg) {
        const __half* src = w_img + (size_t)i * 8192;
        uint32_t dst = smem0 + stg * STAGE_B + 4096;
        #pragma unroll
        for (int j = 0; j < 4; ++j) {
            int f = tid + j * 256;               // 16B units, 0..1023
            CP_ASYNC16(dst + f * 16, src + f * 8);
        }
        CP_COMMIT();
    };

    // ldmatrix lane offsets
    uint32_t aoff[2];
    {
        int m = lane >> 3;
        int tsel = ((m & 1) << 1) | (m >> 1);    // matrix -> tile {0,2,1,3}
        #pragma unroll
        for (int mt = 0; mt < 2; ++mt) {
            int rtm = wm * 4 + mt * 2;
            aoff[mt] = (uint32_t)((rtm * 2 + tsel) * 128 + (lane & 7) * 16);
        }
    }
    // W: per ngroup 4 adjacent tiles (hiK0|hiK1|loK0|loK1); matrix m = tile m
    const uint32_t boff = (uint32_t)((lane >> 3) * 128 + (lane & 7) * 16);

    // ---- prologue: stage 0 = chunk 0 ----
    load_a(0);
    cp_w(0, 0);
    sts_a(0);
    CP_WAIT0();
    __syncthreads();
    if (tid == 0) {
        float s = 0.f;
        #pragma unroll
        for (int i = 0; i < 8; i++) s += sred[i];
        sSb = s;
    }

    float acc[2][8][4];
    #pragma unroll
    for (int mt = 0; mt < 2; ++mt)
        #pragma unroll
        for (int nt = 0; nt < 8; ++nt)
            #pragma unroll
            for (int e = 0; e < 4; ++e) acc[mt][nt][e] = 0.f;

    int st = 0;
    for (int i = 0; i < NCH; ++i) {
        const bool more = (i + 1 < NCH);
        if (more) {
            load_a(i + 1);                 // LDG in flight across MMA phase
            cp_w(i + 1, st ^ 1);
        }

        // ---- MMA on stage st ----
        const uint32_t sb = smem0 + st * STAGE_B;
        uint32_t ah[2][4], al[2][4];
        #pragma unroll
        for (int mt = 0; mt < 2; ++mt) {
            LDSM4(ah[mt], sb + aoff[mt]);
            LDSM4(al[mt], sb + 2048 + aoff[mt]);
        }
        const uint32_t wb = sb + 4096 + wn * 8 * 512 + boff;
        #pragma unroll
        for (int nt = 0; nt < 8; ++nt) {
            uint32_t bq[4];
            LDSM4(bq, wb + nt * 512);
            #pragma unroll
            for (int mt = 0; mt < 2; ++mt) {
                MMAF16(acc[mt][nt], ah[mt], bq[0], bq[1]);   // hi*hi
                MMAF16(acc[mt][nt], ah[mt], bq[2], bq[3]);   // hi*lo
                MMAF16(acc[mt][nt], al[mt], bq[0], bq[1]);   // lo*hi
            }
        }

        if (more) {
            sts_a(st ^ 1);
            CP_WAIT0();
        }
        __syncthreads();
        st ^= 1;
    }

    // Sv: lanes with same lr differ in q -> xor 1,2
    svloc += __shfl_xor_sync(~0u, svloc, 1);
    svloc += __shfl_xor_sync(~0u, svloc, 2);
    if (q == 0) svsum[lr] = svloc;

    // per-thread partial Sg/dg over its 16 columns x 4 rows
    float psg[4] = {0.f, 0.f, 0.f, 0.f};
    float pdg[4] = {0.f, 0.f, 0.f, 0.f};
    const bool isc0 = (wn == 0 && (lane & 3) == 0);   // col0 owner when nt==0
    #pragma unroll
    for (int nt = 0; nt < 8; ++nt) {
        float2 bf = *reinterpret_cast<const float2*>(
            &sbias[wn * 64 + nt * 8 + 2 * (lane & 3)]);
        #pragma unroll
        for (int mt = 0; mt < 2; ++mt) {
            const float* C = acc[mt][nt];
            if (!(isc0 && nt == 0)) {             // exclude column 0
                psg[mt * 2]     = fmaf(C[0], C[0], psg[mt * 2]);
                pdg[mt * 2]     = fmaf(C[0], bf.x, pdg[mt * 2]);
                psg[mt * 2 + 1] = fmaf(C[2], C[2], psg[mt * 2 + 1]);
                pdg[mt * 2 + 1] = fmaf(C[2], bf.x, pdg[mt * 2 + 1]);
            }
            psg[mt * 2]     = fmaf(C[1], C[1], psg[mt * 2]);
            pdg[mt * 2]     = fmaf(C[1], bf.y, pdg[mt * 2]);
            psg[mt * 2 + 1] = fmaf(C[3], C[3], psg[mt * 2 + 1]);
            pdg[mt * 2 + 1] = fmaf(C[3], bf.y, pdg[mt * 2 + 1]);
        }
    }
    #pragma unroll
    for (int e = 0; e < 4; ++e) {
        psg[e] += __shfl_xor_sync(~0u, psg[e], 1);
        psg[e] += __shfl_xor_sync(~0u, psg[e], 2);
        pdg[e] += __shfl_xor_sync(~0u, pdg[e], 1);
        pdg[e] += __shfl_xor_sync(~0u, pdg[e], 2);
    }
    if ((lane & 3) == 0) {
        int r0 = wm * 32 + (lane >> 2);
        sgp[r0][wn]      = psg[0];  sdgp[r0][wn]      = pdg[0];
        sgp[r0 + 8][wn]  = psg[1];  sdgp[r0 + 8][wn]  = pdg[1];
        sgp[r0 + 16][wn] = psg[2];  sdgp[r0 + 16][wn] = pdg[2];
        sgp[r0 + 24][wn] = psg[3];  sdgp[r0 + 24][wn] = pdg[3];
    }
    __syncthreads();

    if (tid < 64) {
        float Sg = sgp[tid][0] + sgp[tid][1] + sgp[tid][2] + sgp[tid][3];
        float dg = sdgp[tid][0] + sdgp[tid][1] + sdgp[tid][2] + sdgp[tid][3];

        const float c   = *cin_p;
        const float c2  = *cout_p;
        const float sqc = sqrtf(c);
        const float sq2 = sqrtf(c2);
        const float Sb  = sSb;
        const float Sv  = svsum[tid];

        const float v0p  = sqrtf(c + Sv);
        const float m    = (sqc * acoshf(fmaxf(v0p / sqc - EPSF, ACOSH_MINF)))
                           / (sqrtf(Sv) + EPSF);
        const float Sw   = m * m * Sg;
        const float dw   = m * dg;
        const float n    = sqrtf(Sw) / sqc + EPSF;
        const float ncl  = fminf(n, CLIPF);
        const float ch   = coshf(ncl);
        const float sfac = sinhf(ncl) / n;
        const float T    = sfac * sfac * Sw;
        const float hp0  = sqrtf(c + T);
        const float dd   = sqc * acoshf(fmaxf(ch, ACOSH_MINF));
        const float d2   = sqc * acoshf(fmaxf(hp0 / sqc - EPSF, ACOSH_MINF));
        const float u0   = sqc - hp0 * hp0 / sqc;
        const float suj2 = (hp0 * hp0 / c) * T;
        const float nrmu = sqrtf(suj2 - u0 * u0);
        const float mlt  = d2 / (nrmu + EPSF);
        const float alph = 1.f - mlt * (hp0 / sqc) * sfac;
        const float m2   = dw / (dd * dd);
        const float beta = alph * m2;
        const float bt0  = -(mlt * u0) * m2;
        const float btsq = bt0 * bt0 + Sb - 2.f * beta * dw + beta * beta * Sw;
        const float nb   = sqrtf(btsq) / sqc + EPSF;
        const float nbcl = fminf(nb, CLIPF);
        const float chb  = coshf(nbcl);
        const float sfb  = sinhf(nbcl) / nb;
        const float gam  = chb * sfac - sfb * beta;
        const float del  = sfb;
        const float Sbi  = gam * gam * Sw + 2.f * gam * del * dw + del * del * Sb;
        const float p0   = sqrtf(c + Sbi);
        const float d3   = sqc * acoshf(fmaxf(p0 / sqc - EPSF, ACOSH_MINF));
        const float qn   = sqrtf(Sbi);
        const float mlt3 = d3 / (qn + EPSF);
        const float nf   = mlt3 * qn / sq2 + EPSF;
        const float nfcl = fminf(nf, CLIPF);
        const float phi  = (sinhf(nfcl) / nf) * mlt3;
        sAw[tid] = phi * gam * m;
        sAb[tid] = phi * del;
        sO0[tid] = sq2 * coshf(nfcl);
    }
    __syncthreads();

    // stores
    #pragma unroll
    for (int mt = 0; mt < 2; ++mt) {
        #pragma unroll
        for (int rp = 0; rp < 2; ++rp) {
            int r = wm * 32 + mt * 16 + rp * 8 + (lane >> 2);
            float Aw = sAw[r], Ab = sAb[r];
            float* orow = out + (size_t)(row0 + r) * D;
            #pragma unroll
            for (int nt = 0; nt < 8; ++nt) {
                float2 bf = *reinterpret_cast<const float2*>(
                    &sbias[wn * 64 + nt * 8 + 2 * (lane & 3)]);
                float g0 = acc[mt][nt][rp * 2];
                float g1 = acc[mt][nt][rp * 2 + 1];
                float2 o;
                o.x = fmaf(Aw, g0, Ab * bf.x);
                o.y = fmaf(Aw, g1, Ab * bf.y);
                if (wn == 0 && nt == 0 && (lane & 3) == 0) o.x = sO0[r];
                *reinterpret_cast<float2*>(
                    orow + wn * 64 + nt * 8 + 2 * (lane & 3)) = o;
            }
        }
    }
}

extern "C" void kernel_launch(void* const* d_in, const int* in_sizes, int n_in,
                              void* d_out, int out_size)
{
    const float* V    = (const float*)d_in[0];
    const float* cin  = (const float*)d_in[1];
    const float* cout = (const float*)d_in[2];
    const float* W    = (const float*)d_in[3];
    const float* bias = (const float*)d_in[4];
    float* out = (float*)d_out;

    const int nrow = in_sizes[0] / D;             // 131072
    const int smem = 2 * STAGE_B;                 // 40 KB dynamic per CTA

    cudaFuncSetAttribute(dh_mma, cudaFuncAttributeMaxDynamicSharedMemorySize, smem);

    prep_w<<<32, 256>>>(W);
    dh_mma<<<nrow / BM, NT, smem>>>(V, cin, cout, bias, out);
}